// round 14
// baseline (speedup 1.0000x reference)
#include <cuda_runtime.h>
#include <cstdint>

// Perona-Malik single diffusion step — PERSISTENT CTAs with double-buffered
// TMA bulk-load pipeline. 592 CTAs (148 SMs x 4); each CTA loops over 4-row
// strips (stride 592) with two 24KB smem buffers: TMA for strip k+2*stride
// is in flight while strip k is computed. Rolling-register compute from
// smem, direct streaming stores.
// out = clamp(image + g * exp(-g^2/K^2) * dt, 0, 1)
// g   = 5-point Laplacian with ReflectionPad2d(1); K=0.1 (1/K^2=100), dt=0.15

#define W 1024
#define H 1024
#define W4 (W / 4)
#define ROWS 4
#define SROWS (ROWS + 2)
#define STRIPS_PER_IMG (H / ROWS)          // 256
#define GRIDX 592                          // 148 SMs * 4 resident CTAs
#define BUF_BYTES (SROWS * W * 4)          // 24576
#define DYN_BYTES (128 + 2 * BUF_BYTES)    // mbarriers + 2 buffers

extern __shared__ __align__(128) char dynsmem[];

__device__ __forceinline__ void stcs4(float4* p, float4 v) {
    asm volatile("st.global.cs.v4.f32 [%0], {%1,%2,%3,%4};"
                 :: "l"(p), "f"(v.x), "f"(v.y), "f"(v.z), "f"(v.w) : "memory");
}

__device__ __forceinline__ void mbar_wait(uint32_t addr, int parity) {
    asm volatile(
        "{\n\t"
        ".reg .pred P;\n\t"
        "WAIT_%=:\n\t"
        "mbarrier.try_wait.parity.acquire.cta.shared::cta.b64 P, [%0], %1, 0x989680;\n\t"
        "@P bra.uni DONE_%=;\n\t"
        "bra.uni WAIT_%=;\n\t"
        "DONE_%=:\n\t"
        "}"
        :: "r"(addr), "r"((uint32_t)parity) : "memory");
}

// Issue the 6 TMA row copies for strip s into the buffer at smem addr baddr,
// completing on the mbarrier at mbaddr. Caller is a single elected thread.
__device__ __forceinline__ void issue_strip(const float* __restrict__ in,
                                            int s, uint32_t baddr,
                                            uint32_t mbaddr) {
    const int n  = s >> 8;                  // s / STRIPS_PER_IMG
    const int y0 = (s & 255) * ROWS;        // strip's first output row
    const float* img = in + (size_t)n * (W * H);

    asm volatile("mbarrier.arrive.expect_tx.shared.b64 _, [%0], %1;"
                 :: "r"(mbaddr), "r"((uint32_t)(SROWS * W * 4)) : "memory");
    #pragma unroll
    for (int j = 0; j < SROWS; j++) {
        int yy = y0 - 1 + j;                // reflect: -1 -> 1, H -> H-2
        yy = (yy < 0) ? 1 : ((yy >= H) ? (2 * H - 2 - yy) : yy);
        const float* src = img + (size_t)yy * W;
        asm volatile(
            "cp.async.bulk.shared::cta.global.mbarrier::complete_tx::bytes "
            "[%0], [%1], %2, [%3];"
            :: "r"(baddr + (uint32_t)(j * W * 4)), "l"(src), "n"(W * 4),
               "r"(mbaddr)
            : "memory");
    }
}

__global__ __launch_bounds__(256, 4)
void pm_kernel(const float* __restrict__ in, float* __restrict__ out,
               int nstrips) {
    const int t   = threadIdx.x;            // float4 column 0..255
    const int cta = blockIdx.x;

    const uint32_t smem0 = (uint32_t)__cvta_generic_to_shared(dynsmem);
    const uint32_t mb0   = smem0;
    const uint32_t mb1   = smem0 + 8;
    const uint32_t bufa[2] = { smem0 + 128, smem0 + 128 + BUF_BYTES };
    float* bufp[2] = { (float*)(dynsmem + 128),
                       (float*)(dynsmem + 128 + BUF_BYTES) };

    if (t == 0) {
        asm volatile("mbarrier.init.shared.b64 [%0], 1;" :: "r"(mb0));
        asm volatile("mbarrier.init.shared.b64 [%0], 1;" :: "r"(mb1));
    }
    __syncthreads();

    // Prologue: fill the 2-deep pipeline.
    if (t == 0) {
        if (cta < nstrips)          issue_strip(in, cta, bufa[0], mb0);
        if (cta + GRIDX < nstrips)  issue_strip(in, cta + GRIDX, bufa[1], mb1);
    }

    int ph0 = 0, ph1 = 0;
    int b = 0;
    for (int s = cta; s < nstrips; s += GRIDX, b ^= 1) {
        const uint32_t mb = b ? mb1 : mb0;
        const int ph = b ? ph1 : ph0;
        mbar_wait(mb, ph);
        if (b) ph1 ^= 1; else ph0 ^= 1;

        const float* buf = bufp[b];
        const int n  = s >> 8;
        const int y0 = (s & 255) * ROWS;
        float* o = out + (size_t)n * (W * H);

        // Rolling-register walk: 1 LDS.128 + 2 scalar LDS per output row.
        float4 a = *(const float4*)&buf[0 * W + 4 * t];
        float4 bb = *(const float4*)&buf[1 * W + 4 * t];

        #pragma unroll
        for (int i = 0; i < ROWS; i++) {
            const float4 d = *(const float4*)&buf[(i + 2) * W + 4 * t];

            // Horizontal halo from smem; image-edge reflection uses the
            // in-register neighbors (left of col0 reflects to col1 = bb.y).
            const float left  = (t == 0)      ? bb.y
                                              : buf[(i + 1) * W + 4 * t - 1];
            const float right = (t == W4 - 1) ? bb.z
                                              : buf[(i + 1) * W + 4 * t + 4];

            float4 g;
            g.x = a.x + d.x + left + bb.y  - 4.0f * bb.x;
            g.y = a.y + d.y + bb.x + bb.z  - 4.0f * bb.y;
            g.z = a.z + d.z + bb.y + bb.w  - 4.0f * bb.z;
            g.w = a.w + d.w + bb.z + right - 4.0f * bb.w;

            float4 r;
            float gg, co, v;
            gg = g.x; co = __expf(-gg * gg * 100.0f);
            v = fmaf(gg * co, 0.15f, bb.x); r.x = fminf(fmaxf(v, 0.0f), 1.0f);
            gg = g.y; co = __expf(-gg * gg * 100.0f);
            v = fmaf(gg * co, 0.15f, bb.y); r.y = fminf(fmaxf(v, 0.0f), 1.0f);
            gg = g.z; co = __expf(-gg * gg * 100.0f);
            v = fmaf(gg * co, 0.15f, bb.z); r.z = fminf(fmaxf(v, 0.0f), 1.0f);
            gg = g.w; co = __expf(-gg * gg * 100.0f);
            v = fmaf(gg * co, 0.15f, bb.w); r.w = fminf(fmaxf(v, 0.0f), 1.0f);

            stcs4((float4*)(o + (size_t)(y0 + i) * W) + t, r);

            a = bb; bb = d;
        }

        // All threads done reading this buffer -> refill it 2 strips ahead.
        __syncthreads();
        if (t == 0 && s + 2 * GRIDX < nstrips)
            issue_strip(in, s + 2 * GRIDX, bufa[b], mb);
    }
}

extern "C" void kernel_launch(void* const* d_in, const int* in_sizes, int n_in,
                              void* d_out, int out_size) {
    const float* image = (const float*)d_in[0];
    // d_in[1] is the fixed 3x3 Laplace kernel; hardcoded in pm_kernel.
    float* out = (float*)d_out;

    const int n_images = in_sizes[0] / (W * H);          // 64
    const int nstrips  = n_images * STRIPS_PER_IMG;      // 16384

    cudaFuncSetAttribute(pm_kernel,
                         cudaFuncAttributeMaxDynamicSharedMemorySize,
                         DYN_BYTES);
    pm_kernel<<<GRIDX, 256, DYN_BYTES>>>(image, out, nstrips);
}

// round 15
// speedup vs baseline: 1.2137x; 1.2137x over previous
#include <cuda_runtime.h>
#include <cstdint>

// Perona-Malik single diffusion step — FINAL (Round-8 configuration).
// TMA bulk-load staging (4 output rows, 6 staged rows = 24KB per block),
// rolling-register compute from smem, direct streaming stores.
// out = clamp(image + g * exp(-g^2/K^2) * dt, 0, 1)
// g   = 5-point Laplacian with ReflectionPad2d(1); K=0.1 (1/K^2=100), dt=0.15
//
// Converged after 14 rounds: six structurally distinct variants (batched
// LDG, register pipelines, TMA one-shot/split/progressive, persistent
// double-buffered) all saturate at ~6.1-6.3 TB/s with DRAM traffic at the
// 512MB floor — this config measured fastest (kernel 76.5us, occ 92%).

#define W 1024
#define H 1024
#define W4 (W / 4)
#define ROWS 4
#define SROWS (ROWS + 2)

__device__ __forceinline__ void stcs4(float4* p, float4 v) {
    asm volatile("st.global.cs.v4.f32 [%0], {%1,%2,%3,%4};"
                 :: "l"(p), "f"(v.x), "f"(v.y), "f"(v.z), "f"(v.w) : "memory");
}

__global__ __launch_bounds__(256, 6)
void pm_kernel(const float* __restrict__ in, float* __restrict__ out) {
    __shared__ __align__(16) float srows[SROWS][W];   // 24 KB
    __shared__ __align__(8) unsigned long long mbar;

    const int y0 = blockIdx.x * ROWS;      // first output row of this block
    const int n  = blockIdx.y;             // image index
    const int t  = threadIdx.x;            // float4 column 0..255

    const float* img = in  + (size_t)n * (W * H);
    float*       o   = out + (size_t)n * (W * H);

    const uint32_t mbar_addr = (uint32_t)__cvta_generic_to_shared(&mbar);

    if (t == 0) {
        asm volatile("mbarrier.init.shared.b64 [%0], 1;" :: "r"(mbar_addr));
    }
    __syncthreads();

    // Elected thread: expect full 24KB, then issue 6 bulk row copies
    // (global -> smem). Rows reflected at volume edges (-1 -> 1, H -> H-2).
    if (t == 0) {
        asm volatile("mbarrier.arrive.expect_tx.shared.b64 _, [%0], %1;"
                     :: "r"(mbar_addr), "r"((uint32_t)(SROWS * W * 4))
                     : "memory");
        #pragma unroll
        for (int j = 0; j < SROWS; j++) {
            int yy = y0 - 1 + j;
            yy = (yy < 0) ? 1 : ((yy >= H) ? (2 * H - 2 - yy) : yy);
            const uint32_t daddr =
                (uint32_t)__cvta_generic_to_shared(&srows[j][0]);
            const float* src = img + (size_t)yy * W;
            asm volatile(
                "cp.async.bulk.shared::cta.global.mbarrier::complete_tx::bytes "
                "[%0], [%1], %2, [%3];"
                :: "r"(daddr), "l"(src), "n"(W * 4), "r"(mbar_addr)
                : "memory");
        }
    }

    // All threads wait for the staged tile (phase parity 0).
    asm volatile(
        "{\n\t"
        ".reg .pred P;\n\t"
        "WAIT_%=:\n\t"
        "mbarrier.try_wait.parity.acquire.cta.shared::cta.b64 P, [%0], 0, 0x989680;\n\t"
        "@P bra.uni DONE_%=;\n\t"
        "bra.uni WAIT_%=;\n\t"
        "DONE_%=:\n\t"
        "}"
        :: "r"(mbar_addr) : "memory");

    // Rolling-register walk down the strip: 1 LDS.128 + 2 scalar LDS per row.
    float4 a = *(const float4*)&srows[0][4 * t];   // row above
    float4 b = *(const float4*)&srows[1][4 * t];   // center row

    #pragma unroll
    for (int i = 0; i < ROWS; i++) {
        const float4 d = *(const float4*)&srows[i + 2][4 * t];

        // Horizontal halo straight from smem; image-edge reflection uses the
        // in-register neighbors (left of col0 reflects to col1 = b.y, etc).
        const float left  = (t == 0)      ? b.y : srows[i + 1][4 * t - 1];
        const float right = (t == W4 - 1) ? b.z : srows[i + 1][4 * t + 4];

        float4 g;
        g.x = a.x + d.x + left + b.y  - 4.0f * b.x;
        g.y = a.y + d.y + b.x  + b.z  - 4.0f * b.y;
        g.z = a.z + d.z + b.y  + b.w  - 4.0f * b.z;
        g.w = a.w + d.w + b.z  + right - 4.0f * b.w;

        float4 r;
        float gg, co, v;
        gg = g.x; co = __expf(-gg * gg * 100.0f);
        v = fmaf(gg * co, 0.15f, b.x); r.x = fminf(fmaxf(v, 0.0f), 1.0f);
        gg = g.y; co = __expf(-gg * gg * 100.0f);
        v = fmaf(gg * co, 0.15f, b.y); r.y = fminf(fmaxf(v, 0.0f), 1.0f);
        gg = g.z; co = __expf(-gg * gg * 100.0f);
        v = fmaf(gg * co, 0.15f, b.z); r.z = fminf(fmaxf(v, 0.0f), 1.0f);
        gg = g.w; co = __expf(-gg * gg * 100.0f);
        v = fmaf(gg * co, 0.15f, b.w); r.w = fminf(fmaxf(v, 0.0f), 1.0f);

        stcs4((float4*)(o + (size_t)(y0 + i) * W) + t, r);

        a = b; b = d;
    }
}

extern "C" void kernel_launch(void* const* d_in, const int* in_sizes, int n_in,
                              void* d_out, int out_size) {
    const float* image = (const float*)d_in[0];
    // d_in[1] is the fixed 3x3 Laplace kernel; hardcoded in pm_kernel.
    float* out = (float*)d_out;

    const int n_images = in_sizes[0] / (W * H);   // 64
    dim3 grid(H / ROWS, n_images);
    pm_kernel<<<grid, 256>>>(image, out);
}

// round 16
// speedup vs baseline: 1.2142x; 1.0004x over previous
#include <cuda_runtime.h>
#include <cstdint>

// Perona-Malik single diffusion step — FINAL (converged, Round-8/15 config).
// TMA bulk-load staging (4 output rows, 6 staged rows = 24KB per block),
// rolling-register compute from smem, direct streaming stores.
// out = clamp(image + g * exp(-g^2/K^2) * dt, 0, 1)
// g   = 5-point Laplacian with ReflectionPad2d(1); K=0.1 (1/K^2=100), dt=0.15
//
// Search converged after 15 rounds: seven structurally distinct variants
// (scalar/batched LDG, register pipelines, TMA one-shot/split/progressive,
// persistent double-buffered) all saturate at 6.1-6.3 TB/s with DRAM traffic
// at the 512MB compulsory floor. This config is the reproducible fastest
// (kernel 76.5us, DRAM 77%, occ 92%, 32 regs).

#define W 1024
#define H 1024
#define W4 (W / 4)
#define ROWS 4
#define SROWS (ROWS + 2)

__device__ __forceinline__ void stcs4(float4* p, float4 v) {
    asm volatile("st.global.cs.v4.f32 [%0], {%1,%2,%3,%4};"
                 :: "l"(p), "f"(v.x), "f"(v.y), "f"(v.z), "f"(v.w) : "memory");
}

__global__ __launch_bounds__(256, 6)
void pm_kernel(const float* __restrict__ in, float* __restrict__ out) {
    __shared__ __align__(16) float srows[SROWS][W];   // 24 KB
    __shared__ __align__(8) unsigned long long mbar;

    const int y0 = blockIdx.x * ROWS;      // first output row of this block
    const int n  = blockIdx.y;             // image index
    const int t  = threadIdx.x;            // float4 column 0..255

    const float* img = in  + (size_t)n * (W * H);
    float*       o   = out + (size_t)n * (W * H);

    const uint32_t mbar_addr = (uint32_t)__cvta_generic_to_shared(&mbar);

    if (t == 0) {
        asm volatile("mbarrier.init.shared.b64 [%0], 1;" :: "r"(mbar_addr));
    }
    __syncthreads();

    // Elected thread: expect full 24KB, then issue 6 bulk row copies
    // (global -> smem). Rows reflected at volume edges (-1 -> 1, H -> H-2).
    if (t == 0) {
        asm volatile("mbarrier.arrive.expect_tx.shared.b64 _, [%0], %1;"
                     :: "r"(mbar_addr), "r"((uint32_t)(SROWS * W * 4))
                     : "memory");
        #pragma unroll
        for (int j = 0; j < SROWS; j++) {
            int yy = y0 - 1 + j;
            yy = (yy < 0) ? 1 : ((yy >= H) ? (2 * H - 2 - yy) : yy);
            const uint32_t daddr =
                (uint32_t)__cvta_generic_to_shared(&srows[j][0]);
            const float* src = img + (size_t)yy * W;
            asm volatile(
                "cp.async.bulk.shared::cta.global.mbarrier::complete_tx::bytes "
                "[%0], [%1], %2, [%3];"
                :: "r"(daddr), "l"(src), "n"(W * 4), "r"(mbar_addr)
                : "memory");
        }
    }

    // All threads wait for the staged tile (phase parity 0).
    asm volatile(
        "{\n\t"
        ".reg .pred P;\n\t"
        "WAIT_%=:\n\t"
        "mbarrier.try_wait.parity.acquire.cta.shared::cta.b64 P, [%0], 0, 0x989680;\n\t"
        "@P bra.uni DONE_%=;\n\t"
        "bra.uni WAIT_%=;\n\t"
        "DONE_%=:\n\t"
        "}"
        :: "r"(mbar_addr) : "memory");

    // Rolling-register walk down the strip: 1 LDS.128 + 2 scalar LDS per row.
    float4 a = *(const float4*)&srows[0][4 * t];   // row above
    float4 b = *(const float4*)&srows[1][4 * t];   // center row

    #pragma unroll
    for (int i = 0; i < ROWS; i++) {
        const float4 d = *(const float4*)&srows[i + 2][4 * t];

        // Horizontal halo straight from smem; image-edge reflection uses the
        // in-register neighbors (left of col0 reflects to col1 = b.y, etc).
        const float left  = (t == 0)      ? b.y : srows[i + 1][4 * t - 1];
        const float right = (t == W4 - 1) ? b.z : srows[i + 1][4 * t + 4];

        float4 g;
        g.x = a.x + d.x + left + b.y  - 4.0f * b.x;
        g.y = a.y + d.y + b.x  + b.z  - 4.0f * b.y;
        g.z = a.z + d.z + b.y  + b.w  - 4.0f * b.z;
        g.w = a.w + d.w + b.z  + right - 4.0f * b.w;

        float4 r;
        float gg, co, v;
        gg = g.x; co = __expf(-gg * gg * 100.0f);
        v = fmaf(gg * co, 0.15f, b.x); r.x = fminf(fmaxf(v, 0.0f), 1.0f);
        gg = g.y; co = __expf(-gg * gg * 100.0f);
        v = fmaf(gg * co, 0.15f, b.y); r.y = fminf(fmaxf(v, 0.0f), 1.0f);
        gg = g.z; co = __expf(-gg * gg * 100.0f);
        v = fmaf(gg * co, 0.15f, b.z); r.z = fminf(fmaxf(v, 0.0f), 1.0f);
        gg = g.w; co = __expf(-gg * gg * 100.0f);
        v = fmaf(gg * co, 0.15f, b.w); r.w = fminf(fmaxf(v, 0.0f), 1.0f);

        stcs4((float4*)(o + (size_t)(y0 + i) * W) + t, r);

        a = b; b = d;
    }
}

extern "C" void kernel_launch(void* const* d_in, const int* in_sizes, int n_in,
                              void* d_out, int out_size) {
    const float* image = (const float*)d_in[0];
    // d_in[1] is the fixed 3x3 Laplace kernel; hardcoded in pm_kernel.
    float* out = (float*)d_out;

    const int n_images = in_sizes[0] / (W * H);   // 64
    dim3 grid(H / ROWS, n_images);
    pm_kernel<<<grid, 256>>>(image, out);
}